// round 13
// baseline (speedup 1.0000x reference)
#include <cuda_runtime.h>
#include <cstdint>

// PolynomialFlowRegularizer: B=64, C=2, H=512, W=512
// err_{b,c} = ( ||f||^2 - rhs^T G^{-1} rhs ) / N  ; out = sum_{b,c} err / B
// cp.async.bulk (TMA) pipeline: DMA-paced 4-stage smem ring per block,
// consumers accumulate from SMEM; fused last-block closed-form finalize.

#define NCH 128                    // B*C = 64*2
#define NPIX (512 * 512)           // 262144
#define CHUNKS 4                   // blocks per channel
#define TPB 256
#define VPC (NPIX / 4)             // 65536 float4 per channel
#define VECS_PER_CHUNK (VPC / CHUNKS)           // 16384
#define TOTAL_BLOCKS (CHUNKS * NCH)             // 512

#define NSTAGE 4
#define STAGE_VECS 512             // float4 per stage = 8KB
#define STAGE_BYTES (STAGE_VECS * 16)
#define ITERS (VECS_PER_CHUNK / STAGE_VECS)     // 32

// per-block partials: [channel][chunk][7] ; 7 = {s2, r0..r5}
__device__ float g_part[NCH * CHUNKS * 7];
__device__ unsigned int g_count = 0;

// ---- compile-time closed-form G^{-1} pieces (grid symmetric, odd moments = 0) ----
constexpr double S0  = 512.0;
constexpr double hh  = 2.0 / 511.0;
constexpr double Si1 = 130816.0;
constexpr double Si2 = 44608256.0;
constexpr double Si3 = 17112825856.0;
constexpr double Si4 = 511.0 * 512.0 * 1023.0 * 784895.0 / 30.0;
constexpr double S2v = S0 - 2.0 * hh * Si1 + hh * hh * Si2;
constexpr double S4v = S0 - 4.0 * hh * Si1 + 6.0 * hh * hh * Si2
                      - 4.0 * hh * hh * hh * Si3 + hh * hh * hh * hh * Si4;
constexpr double Ga = S0 * S0, Gb = S0 * S2v, Gc = S0 * S4v, Gd = S2v * S2v;
constexpr double Gdet = (Gc - Gd) * (Ga * (Gc + Gd) - 2.0 * Gb * Gb);
constexpr double i00  = (Gc * Gc - Gd * Gd) / Gdet;
constexpr double i01  = -Gb * (Gc - Gd) / Gdet;
constexpr double i11  = (Ga * Gc - Gb * Gb) / Gdet;
constexpr double i12  = -(Ga * Gd - Gb * Gb) / Gdet;
constexpr double invXX  = 1.0 / (S0 * S2v);
constexpr double invXY  = 1.0 / (S2v * S2v);
constexpr double OUTSCL = 1.0 / ((double)NPIX * 64.0);

// ---- PTX helpers ----
__device__ __forceinline__ uint32_t smem_u32(const void* p) {
    uint32_t a;
    asm("{ .reg .u64 t; cvta.to.shared.u64 t, %1; cvt.u32.u64 %0, t; }" : "=r"(a) : "l"(p));
    return a;
}
__device__ __forceinline__ void mbar_init(uint32_t mbar, uint32_t count) {
    asm volatile("mbarrier.init.shared.b64 [%0], %1;" :: "r"(mbar), "r"(count) : "memory");
}
__device__ __forceinline__ void mbar_expect_tx(uint32_t mbar, uint32_t bytes) {
    asm volatile("mbarrier.arrive.expect_tx.shared.b64 _, [%0], %1;" :: "r"(mbar), "r"(bytes) : "memory");
}
__device__ __forceinline__ void mbar_arrive(uint32_t mbar) {
    asm volatile("mbarrier.arrive.shared.b64 _, [%0];" :: "r"(mbar) : "memory");
}
__device__ __forceinline__ void mbar_wait(uint32_t mbar, uint32_t parity) {
    asm volatile(
        "{\n\t.reg .pred P1;\n\t"
        "LAB_WAIT_%=:\n\t"
        "mbarrier.try_wait.parity.acquire.cta.shared::cta.b64 P1, [%0], %1;\n\t"
        "@P1 bra.uni LAB_DONE_%=;\n\t"
        "bra.uni LAB_WAIT_%=;\n\t"
        "LAB_DONE_%=:\n\t}"
        :: "r"(mbar), "r"(parity) : "memory");
}
__device__ __forceinline__ void bulk_copy(uint32_t dst_smem, const void* src_gmem, uint32_t mbar) {
    asm volatile(
        "cp.async.bulk.shared::cluster.global.mbarrier::complete_tx::bytes [%0], [%1], %2, [%3];"
        :: "r"(dst_smem), "l"(src_gmem), "n"(STAGE_BYTES), "r"(mbar) : "memory");
}

struct Acc { float s2, r0, r1, r2, r3, r4, r5; };

__device__ __forceinline__ void accum(Acc& a, float4 f, int vg) {   // vg: channel-local vec idx
    const float sc = 2.0f / 511.0f;
    const float yf  = fmaf((float)(vg >> 7), sc, -1.0f);            // row (128 vecs/row)
    const float xf0 = fmaf((float)((vg & 127) << 2), sc, -1.0f);
    const float xf1 = xf0 + sc;
    const float xf2 = xf1 + sc;
    const float xf3 = xf2 + sc;

    const float sf = (f.x + f.y) + (f.z + f.w);
    float sfx  = f.x * xf0;
    sfx = fmaf(f.y, xf1, sfx);
    sfx = fmaf(f.z, xf2, sfx);
    sfx = fmaf(f.w, xf3, sfx);
    float sfx2 = f.x * xf0 * xf0;
    sfx2 = fmaf(f.y * xf1, xf1, sfx2);
    sfx2 = fmaf(f.z * xf2, xf2, sfx2);
    sfx2 = fmaf(f.w * xf3, xf3, sfx2);

    a.s2 = fmaf(f.x, f.x, a.s2);
    a.s2 = fmaf(f.y, f.y, a.s2);
    a.s2 = fmaf(f.z, f.z, a.s2);
    a.s2 = fmaf(f.w, f.w, a.s2);

    a.r0 += sf;
    a.r1 += sfx;
    a.r2 = fmaf(sf, yf, a.r2);
    a.r3 += sfx2;
    a.r4 = fmaf(sfx, yf, a.r4);
    a.r5 = fmaf(sf * yf, yf, a.r5);
}

__global__ __launch_bounds__(TPB) void pfr_tma(const float4* __restrict__ in,
                                               float* __restrict__ out) {
    __shared__ __align__(128) float4 s_buf[NSTAGE * STAGE_VECS];   // 32 KB
    __shared__ __align__(8) unsigned long long s_full[NSTAGE], s_empty[NSTAGE];

    const int chunk = blockIdx.x;   // 0..CHUNKS-1
    const int bc    = blockIdx.y;   // 0..NCH-1
    const int t     = threadIdx.x;

    const float4* base = in + (size_t)bc * VPC + (size_t)chunk * VECS_PER_CHUNK;
    const int vgbase   = chunk * VECS_PER_CHUNK;

    uint32_t full[NSTAGE], empty[NSTAGE];
#pragma unroll
    for (int s = 0; s < NSTAGE; s++) {
        full[s]  = smem_u32(&s_full[s]);
        empty[s] = smem_u32(&s_empty[s]);
    }

    if (t == 0) {
#pragma unroll
        for (int s = 0; s < NSTAGE; s++) {
            mbar_init(full[s], 1);        // completes on expect_tx bytes
            mbar_init(empty[s], TPB);     // completes when all threads consumed
        }
    }
    __syncthreads();

    // prologue: fill all stages (round 0)
    if (t == 0) {
#pragma unroll
        for (int s = 0; s < NSTAGE; s++) {
            mbar_expect_tx(full[s], STAGE_BYTES);
            bulk_copy(smem_u32(&s_buf[s * STAGE_VECS]), base + s * STAGE_VECS, full[s]);
        }
    }

    Acc a = {0.f, 0.f, 0.f, 0.f, 0.f, 0.f, 0.f};

    for (int it = 0; it < ITERS; it++) {
        const int s   = it & (NSTAGE - 1);
        const int par = (it >> 2) & 1;          // NSTAGE = 4

        mbar_wait(full[s], par);

        float4 f0 = s_buf[s * STAGE_VECS + t];
        float4 f1 = s_buf[s * STAGE_VECS + t + TPB];
        accum(a, f0, vgbase + it * STAGE_VECS + t);
        accum(a, f1, vgbase + it * STAGE_VECS + t + TPB);

        mbar_arrive(empty[s]);

        if (t == 0 && it + NSTAGE < ITERS) {
            mbar_wait(empty[s], par);           // all TPB consumed this round
            mbar_expect_tx(full[s], STAGE_BYTES);
            bulk_copy(smem_u32(&s_buf[s * STAGE_VECS]),
                      base + (it + NSTAGE) * STAGE_VECS, full[s]);
        }
    }

    // ---- block-local deterministic reduction ----
    float vals[7] = {a.s2, a.r0, a.r1, a.r2, a.r3, a.r4, a.r5};
#pragma unroll
    for (int i = 0; i < 7; i++) {
#pragma unroll
        for (int off = 16; off > 0; off >>= 1)
            vals[i] += __shfl_down_sync(0xFFFFFFFFu, vals[i], off);
    }

    __shared__ float sh[8][7];  // 8 warps
    const int warp = t >> 5;
    const int lane = t & 31;
    if (lane == 0) {
#pragma unroll
        for (int i = 0; i < 7; i++) sh[warp][i] = vals[i];
    }
    __syncthreads();

    if (t == 0) {
        float* dst = &g_part[((size_t)bc * CHUNKS + chunk) * 7];
#pragma unroll
        for (int i = 0; i < 7; i++) {
            float s = sh[0][i];
#pragma unroll
            for (int w = 1; w < 8; w++) s += sh[w][i];
            dst[i] = s;
        }
    }

    // ---- last-block finalize (threadfence-reduction pattern) ----
    __shared__ bool amLast;
    __threadfence();
    if (t == 0)
        amLast = (atomicAdd(&g_count, 1u) == TOTAL_BLOCKS - 1);
    __syncthreads();
    if (!amLast) return;

    if (t == 0) g_count = 0;         // reset for next graph replay
    __threadfence();

    // one thread per channel: fold 4 chunk-partials in double
    double err = 0.0;
    if (t < NCH) {
        double s[7] = {0, 0, 0, 0, 0, 0, 0};
#pragma unroll
        for (int cc = 0; cc < CHUNKS; cc++) {
            const float* p = &g_part[((size_t)t * CHUNKS + cc) * 7];
#pragma unroll
            for (int i = 0; i < 7; i++) s[i] += (double)__ldcg(&p[i]);
        }
        const double m0 = s[1], mx = s[2], my = s[3], mxx = s[4], mxy = s[5], myy = s[6];
        double quad = (mx * mx + my * my) * invXX + mxy * mxy * invXY;
        quad += i00 * m0 * m0 + 2.0 * i01 * m0 * (mxx + myy)
              + i11 * (mxx * mxx + myy * myy) + 2.0 * i12 * mxx * myy;
        err = s[0] - quad;
    }

    // deterministic tree reduction across 128 channels
#pragma unroll
    for (int off = 16; off > 0; off >>= 1)
        err += __shfl_down_sync(0xFFFFFFFFu, err, off);

    __shared__ double wsum[4];
    if (lane == 0 && warp < 4) wsum[warp] = err;
    __syncthreads();

    if (t == 0) {
        double total = wsum[0] + wsum[1] + wsum[2] + wsum[3];
        out[0] = (float)(total * OUTSCL);
    }
}

extern "C" void kernel_launch(void* const* d_in, const int* in_sizes, int n_in,
                              void* d_out, int out_size) {
    (void)in_sizes; (void)n_in; (void)out_size;
    const float4* in = (const float4*)d_in[0];
    float* out = (float*)d_out;
    pfr_tma<<<dim3(CHUNKS, NCH), TPB>>>(in, out);
}

// round 16
// speedup vs baseline: 1.3075x; 1.3075x over previous
#include <cuda_runtime.h>

// PolynomialFlowRegularizer: B=64, C=2, H=512, W=512
// err_{b,c} = ( ||f||^2 - rhs^T G^{-1} rhs ) / N  ; out = sum_{b,c} err / B
// Fused kernel: MLP=8 streaming + deferred-x factorized accumulators
// (19 ops/float4 vs 34) + last-block closed-form finalize.

#define NCH 128                    // B*C = 64*2
#define NPIX (512 * 512)           // 262144
#define CHUNKS 4                   // blocks per channel
#define TPB 256
#define VPC (NPIX / 4)             // 65536 float4 per channel
#define VECS_PER_CHUNK (VPC / CHUNKS)           // 16384 (= 128 rows)
#define MLP 8
#define BATCHES (VECS_PER_CHUNK / (MLP * TPB))  // 8
#define TOTAL_BLOCKS (CHUNKS * NCH)             // 512

// per-block partials: [channel][chunk][7] ; 7 = {s2, r0..r5}
__device__ float g_part[NCH * CHUNKS * 7];
__device__ unsigned int g_count = 0;

// ---- compile-time closed-form G^{-1} pieces (grid symmetric, odd moments = 0) ----
constexpr double S0d = 512.0;
constexpr double hh  = 2.0 / 511.0;
constexpr double Si1 = 130816.0;
constexpr double Si2 = 44608256.0;
constexpr double Si3 = 17112825856.0;
constexpr double Si4 = 511.0 * 512.0 * 1023.0 * 784895.0 / 30.0;
constexpr double S2v = S0d - 2.0 * hh * Si1 + hh * hh * Si2;
constexpr double S4v = S0d - 4.0 * hh * Si1 + 6.0 * hh * hh * Si2
                      - 4.0 * hh * hh * hh * Si3 + hh * hh * hh * hh * Si4;
constexpr double Ga = S0d * S0d, Gb = S0d * S2v, Gc = S0d * S4v, Gd = S2v * S2v;
constexpr double Gdet = (Gc - Gd) * (Ga * (Gc + Gd) - 2.0 * Gb * Gb);
constexpr double i00  = (Gc * Gc - Gd * Gd) / Gdet;
constexpr double i01  = -Gb * (Gc - Gd) / Gdet;
constexpr double i11  = (Ga * Gc - Gb * Gb) / Gdet;
constexpr double i12  = -(Ga * Gd - Gb * Gb) / Gdet;
constexpr double invXX  = 1.0 / (S0d * S2v);
constexpr double invXY  = 1.0 / (S2v * S2v);
constexpr double OUTSCL = 1.0 / ((double)NPIX * 64.0);

__global__ __launch_bounds__(TPB) void pfr_fused(const float4* __restrict__ in,
                                                 float* __restrict__ out) {
    const int chunk = blockIdx.x;   // 0..CHUNKS-1
    const int bc    = blockIdx.y;   // 0..NCH-1
    const int t     = threadIdx.x;

    const float sc = 2.0f / 511.0f;

    // thread-fixed x columns: col = t&127 (4 pixels), half = t>>7 selects row parity
    const int col  = t & 127;
    const int half = t >> 7;
    const float x0 = fmaf((float)(col << 2), sc, -1.0f);
    const float x1 = x0 + sc, x2 = x1 + sc, x3 = x2 + sc;
    const float q0 = x0 * x0, q1 = x1 * x1, q2 = x2 * x2, q3 = x3 * x3;

    const float4* tb = in + (size_t)bc * VPC + (size_t)chunk * VECS_PER_CHUNK + t;
    const int row0 = chunk * 128 + half;      // channel row of this thread's first load

    // deferred-x accumulators
    float S0 = 0.f, S1 = 0.f, S2 = 0.f, S3 = 0.f;   // plain component sums
    float T0 = 0.f, T1 = 0.f, T2 = 0.f, T3 = 0.f;   // y-weighted
    float U0 = 0.f, U1 = 0.f, U2 = 0.f, U3 = 0.f;   // y^2-weighted
    float s2 = 0.f;                                  // ||f||^2

    for (int k = 0; k < BATCHES; k++) {
        float4 f[MLP];
#pragma unroll
        for (int j = 0; j < MLP; j++)               // front-batched: explicit MLP=8
            f[j] = tb[k * (MLP * TPB) + j * TPB];

#pragma unroll
        for (int j = 0; j < MLP; j++) {
            const int row = row0 + k * (2 * MLP) + j * 2;   // 2 rows per 256 vecs
            const float yf = fmaf((float)row, sc, -1.0f);
            const float y2 = yf * yf;

            S0 += f[j].x;  S1 += f[j].y;  S2 += f[j].z;  S3 += f[j].w;
            T0 = fmaf(f[j].x, yf, T0);  T1 = fmaf(f[j].y, yf, T1);
            T2 = fmaf(f[j].z, yf, T2);  T3 = fmaf(f[j].w, yf, T3);
            U0 = fmaf(f[j].x, y2, U0);  U1 = fmaf(f[j].y, y2, U1);
            U2 = fmaf(f[j].z, y2, U2);  U3 = fmaf(f[j].w, y2, U3);
            s2 = fmaf(f[j].x, f[j].x, s2);  s2 = fmaf(f[j].y, f[j].y, s2);
            s2 = fmaf(f[j].z, f[j].z, s2);  s2 = fmaf(f[j].w, f[j].w, s2);
        }
    }

    // end-of-loop x folds (per-thread constants)
    const float r0 = (S0 + S1) + (S2 + S3);
    float r1 = x0 * S0; r1 = fmaf(x1, S1, r1); r1 = fmaf(x2, S2, r1); r1 = fmaf(x3, S3, r1);
    float r3 = q0 * S0; r3 = fmaf(q1, S1, r3); r3 = fmaf(q2, S2, r3); r3 = fmaf(q3, S3, r3);
    const float r2 = (T0 + T1) + (T2 + T3);
    float r4 = x0 * T0; r4 = fmaf(x1, T1, r4); r4 = fmaf(x2, T2, r4); r4 = fmaf(x3, T3, r4);
    const float r5 = (U0 + U1) + (U2 + U3);

    // ---- block-local deterministic reduction ----
    float vals[7] = {s2, r0, r1, r2, r3, r4, r5};
#pragma unroll
    for (int i = 0; i < 7; i++) {
#pragma unroll
        for (int off = 16; off > 0; off >>= 1)
            vals[i] += __shfl_down_sync(0xFFFFFFFFu, vals[i], off);
    }

    __shared__ float sh[8][7];  // 8 warps
    const int warp = t >> 5;
    const int lane = t & 31;
    if (lane == 0) {
#pragma unroll
        for (int i = 0; i < 7; i++) sh[warp][i] = vals[i];
    }
    __syncthreads();

    if (t == 0) {
        float* dst = &g_part[((size_t)bc * CHUNKS + chunk) * 7];
#pragma unroll
        for (int i = 0; i < 7; i++) {
            float s = sh[0][i];
#pragma unroll
            for (int w = 1; w < 8; w++) s += sh[w][i];
            dst[i] = s;
        }
    }

    // ---- last-block finalize (threadfence-reduction pattern) ----
    __shared__ bool amLast;
    __threadfence();
    if (t == 0)
        amLast = (atomicAdd(&g_count, 1u) == TOTAL_BLOCKS - 1);
    __syncthreads();
    if (!amLast) return;

    if (t == 0) g_count = 0;         // reset for next graph replay
    __threadfence();

    // one thread per channel: fold 4 chunk-partials in double
    double err = 0.0;
    if (t < NCH) {
        double s[7] = {0, 0, 0, 0, 0, 0, 0};
#pragma unroll
        for (int cc = 0; cc < CHUNKS; cc++) {
            const float* p = &g_part[((size_t)t * CHUNKS + cc) * 7];
#pragma unroll
            for (int i = 0; i < 7; i++) s[i] += (double)__ldcg(&p[i]);
        }
        const double m0 = s[1], mx = s[2], my = s[3], mxx = s[4], mxy = s[5], myy = s[6];
        double quad = (mx * mx + my * my) * invXX + mxy * mxy * invXY;
        quad += i00 * m0 * m0 + 2.0 * i01 * m0 * (mxx + myy)
              + i11 * (mxx * mxx + myy * myy) + 2.0 * i12 * mxx * myy;
        err = s[0] - quad;
    }

    // deterministic tree reduction across 128 channels
#pragma unroll
    for (int off = 16; off > 0; off >>= 1)
        err += __shfl_down_sync(0xFFFFFFFFu, err, off);

    __shared__ double wsum[4];
    if (lane == 0 && warp < 4) wsum[warp] = err;
    __syncthreads();

    if (t == 0) {
        double total = wsum[0] + wsum[1] + wsum[2] + wsum[3];
        out[0] = (float)(total * OUTSCL);
    }
}

extern "C" void kernel_launch(void* const* d_in, const int* in_sizes, int n_in,
                              void* d_out, int out_size) {
    (void)in_sizes; (void)n_in; (void)out_size;
    const float4* in = (const float4*)d_in[0];
    float* out = (float*)d_out;
    pfr_fused<<<dim3(CHUNKS, NCH), TPB>>>(in, out);
}